// round 2
// baseline (speedup 1.0000x reference)
#include <cuda_runtime.h>
#include <cuda_bf16.h>
#include <cstdint>

// Problem constants (B=256, N=128, D=512)
#define BN    32768
#define DIM   512

// ---------------- device scratch (no allocations allowed) ----------------
__device__ float  g_G[DIM * DIM];   // Gram matrix X^T X, fp32
__device__ double g_T;              // trace(G * V V^T)
__device__ double g_half;           // 0.5 * sum_d G_dd * r_d

// ---------------- helpers ----------------
__device__ __forceinline__ unsigned smem_u32(const void* p) {
    return (unsigned)__cvta_generic_to_shared(p);
}

__device__ __forceinline__ unsigned pack_bf16x2(float a, float b) {
    __nv_bfloat162 h = __floats2bfloat162_rn(a, b);  // .x = a (low), .y = b (high)
    return *reinterpret_cast<unsigned*>(&h);
}

__device__ __forceinline__ void ldsm4t(unsigned* r, unsigned addr) {
    asm volatile("ldmatrix.sync.aligned.m8n8.x4.trans.shared.b16 {%0,%1,%2,%3}, [%4];"
                 : "=r"(r[0]), "=r"(r[1]), "=r"(r[2]), "=r"(r[3])
                 : "r"(addr));
}

__device__ __forceinline__ void mma16816(float* c, const unsigned* a, unsigned b0, unsigned b1) {
    asm volatile(
        "mma.sync.aligned.m16n8k16.row.col.f32.bf16.bf16.f32 "
        "{%0,%1,%2,%3}, {%4,%5,%6,%7}, {%8,%9}, {%0,%1,%2,%3};"
        : "+f"(c[0]), "+f"(c[1]), "+f"(c[2]), "+f"(c[3])
        : "r"(a[0]), "r"(a[1]), "r"(a[2]), "r"(a[3]), "r"(b0), "r"(b1));
}

// ---------------- K0: zero scratch ----------------
__global__ void k_zero() {
    int idx = blockIdx.x * 256 + threadIdx.x;      // 65536 threads
#pragma unroll
    for (int i = 0; i < 4; i++) g_G[idx + i * 65536] = 0.f;
    if (idx == 0) { g_T = 0.0; g_half = 0.0; }
}

// ---------------- K1: linear part out[row] = dot(x_row, W) + b ----------------
__global__ __launch_bounds__(256) void k_linear(const float* __restrict__ x,
                                                const float* __restrict__ W,
                                                const float* __restrict__ bias,
                                                float* __restrict__ out) {
    __shared__ float sW[DIM];
    int tid = threadIdx.x;
    for (int i = tid; i < DIM; i += 256) sW[i] = W[i];
    __syncthreads();

    int warp = tid >> 5, lane = tid & 31;
    int row = blockIdx.x * 8 + warp;               // 4096 blocks * 8 rows
    const float4* xr = reinterpret_cast<const float4*>(x + (size_t)row * DIM);
    const float4* wr = reinterpret_cast<const float4*>(sW);
    float s = 0.f;
#pragma unroll
    for (int j = 0; j < 4; j++) {
        float4 a = xr[lane + j * 32];
        float4 w = wr[lane + j * 32];
        s += a.x * w.x + a.y * w.y + a.z * w.z + a.w * w.w;
    }
#pragma unroll
    for (int off = 16; off; off >>= 1) s += __shfl_xor_sync(0xffffffffu, s, off);
    if (lane == 0) out[row] = s + bias[0];
}

// ---------------- K2: Gram = X^T X via bf16 mma.sync ----------------
// Output 512x512 split into 16 tiles of 128x128; 16 k-splits of 2048 rows each.
// 256 CTAs of 256 threads (8 warps; warp tile 64x32 in a 2x4 warp grid).
#define TKB    32           // k rows staged per iteration
#define LDP    136          // SMEM pitch in bf16 elements (128 + 8 pad -> conflict-free ldmatrix)
#define KCHUNK 2048
#define NSTAGE (KCHUNK / TKB)

__global__ __launch_bounds__(256) void k_gram(const float* __restrict__ x) {
    __shared__ __nv_bfloat16 sA[2][TKB * LDP];
    __shared__ __nv_bfloat16 sB[2][TKB * LDP];

    const int tid  = threadIdx.x;
    const int bid  = blockIdx.x;
    const int tile = bid & 15;          // 16 output tiles
    const int ks   = bid >> 4;          // 16 k-splits
    const int mt = tile >> 2, nt = tile & 3;
    const int m0 = mt * 128, n0 = nt * 128;
    const int kbase = ks * KCHUNK;

    const int lane = tid & 31, warp = tid >> 5;
    const int wm0 = (warp >> 2) * 64;   // warp m offset (0 / 64)
    const int wn0 = (warp & 3) * 32;    // warp n offset (0/32/64/96)

    // ldmatrix lane mapping
    const int sub = lane >> 3, r8 = lane & 7;
    const int lmk = r8 + ((sub >> 1) << 3);        // k offset within 16
    const int lmc = (sub & 1) << 3;                // col offset within 16
    const unsigned lmoff = (unsigned)((lmk * LDP + lmc) * 2);

    float acc[4][4][4];
#pragma unroll
    for (int i = 0; i < 4; i++)
#pragma unroll
        for (int j = 0; j < 4; j++)
#pragma unroll
            for (int q = 0; q < 4; q++) acc[i][j][q] = 0.f;

    float4 pa[4], pb[4];

    // prefetch helper (stage s)
    auto gload = [&](int s) {
#pragma unroll
        for (int i = 0; i < 4; i++) {
            int idx = tid + i * 256;
            int row = idx >> 5, c4 = idx & 31;
            const float* base = x + (size_t)(kbase + s * TKB + row) * DIM + c4 * 4;
            pa[i] = *reinterpret_cast<const float4*>(base + m0);
            pb[i] = *reinterpret_cast<const float4*>(base + n0);
        }
    };
    auto sstore = [&](int buf) {
#pragma unroll
        for (int i = 0; i < 4; i++) {
            int idx = tid + i * 256;
            int row = idx >> 5, c4 = idx & 31;
            unsigned* da = reinterpret_cast<unsigned*>(&sA[buf][row * LDP + c4 * 4]);
            unsigned* db = reinterpret_cast<unsigned*>(&sB[buf][row * LDP + c4 * 4]);
            da[0] = pack_bf16x2(pa[i].x, pa[i].y);
            da[1] = pack_bf16x2(pa[i].z, pa[i].w);
            db[0] = pack_bf16x2(pb[i].x, pb[i].y);
            db[1] = pack_bf16x2(pb[i].z, pb[i].w);
        }
    };

    gload(0);
    sstore(0);
    __syncthreads();

    for (int s = 0; s < NSTAGE; s++) {
        const int buf = s & 1;
        if (s + 1 < NSTAGE) gload(s + 1);

        const unsigned baseA = smem_u32(&sA[buf][0]) + lmoff;
        const unsigned baseB = smem_u32(&sB[buf][0]) + lmoff;
#pragma unroll
        for (int kk = 0; kk < TKB; kk += 16) {
            unsigned afr[4][4];
#pragma unroll
            for (int mi = 0; mi < 4; mi++)
                ldsm4t(afr[mi], baseA + (unsigned)((kk * LDP + wm0 + mi * 16) * 2));
            unsigned bq[2][4];
#pragma unroll
            for (int nb = 0; nb < 2; nb++)
                ldsm4t(bq[nb], baseB + (unsigned)((kk * LDP + wn0 + nb * 16) * 2));
#pragma unroll
            for (int mi = 0; mi < 4; mi++) {
                mma16816(acc[mi][0], afr[mi], bq[0][0], bq[0][2]);
                mma16816(acc[mi][1], afr[mi], bq[0][1], bq[0][3]);
                mma16816(acc[mi][2], afr[mi], bq[1][0], bq[1][2]);
                mma16816(acc[mi][3], afr[mi], bq[1][1], bq[1][3]);
            }
        }
        if (s + 1 < NSTAGE) sstore((s + 1) & 1);
        __syncthreads();
    }

    // epilogue: atomic-add accumulators into global G
    const int g = lane >> 2, t4 = lane & 3;
#pragma unroll
    for (int mi = 0; mi < 4; mi++) {
#pragma unroll
        for (int ni = 0; ni < 4; ni++) {
            int row0 = m0 + wm0 + mi * 16 + g;
            int col0 = n0 + wn0 + ni * 8 + 2 * t4;
            atomicAdd(&g_G[row0 * DIM + col0],           acc[mi][ni][0]);
            atomicAdd(&g_G[row0 * DIM + col0 + 1],       acc[mi][ni][1]);
            atomicAdd(&g_G[(row0 + 8) * DIM + col0],     acc[mi][ni][2]);
            atomicAdd(&g_G[(row0 + 8) * DIM + col0 + 1], acc[mi][ni][3]);
        }
    }
}

// ---------------- K3: T = sum_{d,d'} G[d][d'] * (V V^T)[d][d'] ----------------
// 64 tiles of 64x64 over (d,d'), 4 e-splits of 128 -> 256 CTAs.
__global__ __launch_bounds__(256) void k_trace(const float* __restrict__ V) {
    __shared__ float sVa[64 * 33];
    __shared__ float sVb[64 * 33];
    __shared__ float red[256];

    const int bid  = blockIdx.x;
    const int tile = bid >> 2, es = bid & 3;
    const int di = (tile >> 3) * 64, dj = (tile & 7) * 64;
    const int e0 = es * 128;
    const int tid = threadIdx.x;
    const int tr = tid >> 4, tc = tid & 15;

    float acc[4][4];
#pragma unroll
    for (int i = 0; i < 4; i++)
#pragma unroll
        for (int j = 0; j < 4; j++) acc[i][j] = 0.f;

    for (int ch = 0; ch < 4; ch++) {
        __syncthreads();
#pragma unroll
        for (int i = 0; i < 8; i++) {
            int idx = tid + i * 256;           // 2048 floats each
            int rr = idx >> 5, cc = idx & 31;
            sVa[rr * 33 + cc] = V[(size_t)(di + rr) * DIM + e0 + ch * 32 + cc];
            sVb[rr * 33 + cc] = V[(size_t)(dj + rr) * DIM + e0 + ch * 32 + cc];
        }
        __syncthreads();
#pragma unroll 8
        for (int ec = 0; ec < 32; ec++) {
            float av[4], bv[4];
#pragma unroll
            for (int i = 0; i < 4; i++) av[i] = sVa[(tr * 4 + i) * 33 + ec];
#pragma unroll
            for (int j = 0; j < 4; j++) bv[j] = sVb[(tc * 4 + j) * 33 + ec];
#pragma unroll
            for (int i = 0; i < 4; i++)
#pragma unroll
                for (int j = 0; j < 4; j++) acc[i][j] += av[i] * bv[j];
        }
    }

    float t = 0.f;
#pragma unroll
    for (int i = 0; i < 4; i++)
#pragma unroll
        for (int j = 0; j < 4; j++)
            t += acc[i][j] * g_G[(di + tr * 4 + i) * DIM + dj + tc * 4 + j];

    red[tid] = t;
    __syncthreads();
    for (int o = 128; o; o >>= 1) {
        if (tid < o) red[tid] += red[tid + o];
        __syncthreads();
    }
    if (tid == 0) atomicAdd(&g_T, (double)red[0]);
}

// ---------------- K3b: g_half = 0.5 * sum_d G_dd * (sum_e V[d][e]^2) ----------------
__global__ __launch_bounds__(256) void k_diag(const float* __restrict__ V) {
    const int warp = threadIdx.x >> 5, lane = threadIdx.x & 31;
    const int d = blockIdx.x * 8 + warp;          // 64 blocks
    const float* row = V + (size_t)d * DIM;
    float s = 0.f;
#pragma unroll
    for (int i = 0; i < 16; i++) {
        float v = row[lane + i * 32];
        s += v * v;
    }
#pragma unroll
    for (int off = 16; off; off >>= 1) s += __shfl_xor_sync(0xffffffffu, s, off);
    if (lane == 0) atomicAdd(&g_half, 0.5 * (double)s * (double)g_G[d * (DIM + 1)]);
}

// ---------------- K4: broadcast-add the interaction scalar ----------------
__global__ void k_final(float* __restrict__ out) {
    int i = blockIdx.x * 256 + threadIdx.x;       // 128 blocks
    float I = (float)(g_half - g_T);
    out[i] += I;
}

// ---------------- launch ----------------
extern "C" void kernel_launch(void* const* d_in, const int* in_sizes, int n_in,
                              void* d_out, int out_size) {
    const float* x = (const float*)d_in[0];   // [256,128,512]
    const float* W = (const float*)d_in[1];   // [1,512]
    const float* b = (const float*)d_in[2];   // [1]
    const float* V = (const float*)d_in[3];   // [512,512]
    float* out = (float*)d_out;               // [32768,1]

    k_zero  <<<256, 256>>>();
    k_linear<<<BN / 8, 256>>>(x, W, b, out);
    k_gram  <<<256, 256>>>(x);
    k_trace <<<256, 256>>>(V);
    k_diag  <<<64, 256>>>(V);
    k_final <<<BN / 256, 256>>>(out);
}

// round 3
// speedup vs baseline: 1.0354x; 1.0354x over previous
#include <cuda_runtime.h>
#include <cuda_bf16.h>
#include <cstdint>

// Problem constants (B=256, N=128, D=512)
#define BN    32768
#define DIM   512

// ---------------- device scratch (no allocations allowed) ----------------
__device__ __nv_bfloat16 g_xb[BN * DIM];   // bf16 copy of x (33.5 MB, fits L2)
__device__ float  g_E[DIM * DIM];          // E = 0.5*diag(r) - V V^T, fp32
__device__ double g_S;                     // sum G .* E  (the interaction scalar)

__device__ const int c_mt[10] = {0,0,0,0,1,1,1,2,2,3};
__device__ const int c_nt[10] = {0,1,2,3,1,2,3,2,3,3};

// ---------------- helpers ----------------
__device__ __forceinline__ unsigned smem_u32(const void* p) {
    return (unsigned)__cvta_generic_to_shared(p);
}

__device__ __forceinline__ unsigned pack_bf16x2(float a, float b) {
    __nv_bfloat162 h = __floats2bfloat162_rn(a, b);
    return *reinterpret_cast<unsigned*>(&h);
}

__device__ __forceinline__ void ldsm4t(unsigned* r, unsigned addr) {
    asm volatile("ldmatrix.sync.aligned.m8n8.x4.trans.shared.b16 {%0,%1,%2,%3}, [%4];"
                 : "=r"(r[0]), "=r"(r[1]), "=r"(r[2]), "=r"(r[3])
                 : "r"(addr));
}

__device__ __forceinline__ void mma16816(float* c, const unsigned* a, unsigned b0, unsigned b1) {
    asm volatile(
        "mma.sync.aligned.m16n8k16.row.col.f32.bf16.bf16.f32 "
        "{%0,%1,%2,%3}, {%4,%5,%6,%7}, {%8,%9}, {%0,%1,%2,%3};"
        : "+f"(c[0]), "+f"(c[1]), "+f"(c[2]), "+f"(c[3])
        : "r"(a[0]), "r"(a[1]), "r"(a[2]), "r"(a[3]), "r"(b0), "r"(b1));
}

// ---------------- K0: zero the scalar accumulator ----------------
__global__ void k_zero() {
    if (threadIdx.x == 0) g_S = 0.0;
}

// ---------------- K1: linear part + bf16 conversion (single x pass) -------
__global__ __launch_bounds__(256) void k_fuse(const float* __restrict__ x,
                                              const float* __restrict__ W,
                                              const float* __restrict__ bias,
                                              float* __restrict__ out) {
    __shared__ float sW[DIM];
    int tid = threadIdx.x;
    for (int i = tid; i < DIM; i += 256) sW[i] = W[i];
    __syncthreads();

    int warp = tid >> 5, lane = tid & 31;
    int row = blockIdx.x * 8 + warp;               // 4096 blocks * 8 rows
    const float4* xr = reinterpret_cast<const float4*>(x + (size_t)row * DIM);
    const float4* wr = reinterpret_cast<const float4*>(sW);
    uint2* xbr = reinterpret_cast<uint2*>(g_xb + (size_t)row * DIM);
    float s = 0.f;
#pragma unroll
    for (int j = 0; j < 4; j++) {
        float4 a = xr[lane + j * 32];
        float4 w = wr[lane + j * 32];
        s += a.x * w.x + a.y * w.y + a.z * w.z + a.w * w.w;
        uint2 p;
        p.x = pack_bf16x2(a.x, a.y);
        p.y = pack_bf16x2(a.z, a.w);
        xbr[lane + j * 32] = p;
    }
#pragma unroll
    for (int off = 16; off; off >>= 1) s += __shfl_xor_sync(0xffffffffu, s, off);
    if (lane == 0) out[row] = s + bias[0];
}

// ---------------- K2: E = 0.5*diag(r) - V V^T  (fp32, float4 LDS) --------
// 64 CTAs, each a 64x64 tile of E, full e-range. smem holds V^T chunks.
__global__ __launch_bounds__(256) void k_E(const float* __restrict__ V) {
    __shared__ float sVa[32 * 68];   // [e-chunk 32][64 rows + 4 pad] -> float4 aligned
    __shared__ float sVb[32 * 68];

    const int bid = blockIdx.x;
    const int di = (bid >> 3) * 64, dj = (bid & 7) * 64;
    const int tid = threadIdx.x;
    const int tr = tid >> 4, tc = tid & 15;

    float acc[4][4];
#pragma unroll
    for (int i = 0; i < 4; i++)
#pragma unroll
        for (int j = 0; j < 4; j++) acc[i][j] = 0.f;

    for (int ch = 0; ch < 16; ch++) {            // 16 chunks of 32 e-values
        __syncthreads();
#pragma unroll
        for (int i = 0; i < 8; i++) {
            int idx = tid + i * 256;             // 2048 per buffer
            int rr = idx >> 5, cc = idx & 31;
            sVa[cc * 68 + rr] = V[(size_t)(di + rr) * DIM + ch * 32 + cc];
            sVb[cc * 68 + rr] = V[(size_t)(dj + rr) * DIM + ch * 32 + cc];
        }
        __syncthreads();
#pragma unroll 4
        for (int ec = 0; ec < 32; ec++) {
            float4 av = reinterpret_cast<const float4*>(sVa)[ec * 17 + tr];
            float4 bv = reinterpret_cast<const float4*>(sVb)[ec * 17 + tc];
            float a4[4] = {av.x, av.y, av.z, av.w};
            float b4[4] = {bv.x, bv.y, bv.z, bv.w};
#pragma unroll
            for (int i = 0; i < 4; i++)
#pragma unroll
                for (int j = 0; j < 4; j++) acc[i][j] += a4[i] * b4[j];
        }
    }

    // E = 0.5*diag(r) - C ; on the diagonal E_dd = -0.5*C_dd
#pragma unroll
    for (int i = 0; i < 4; i++) {
        int row = di + tr * 4 + i;
        float4 e;
        float ev[4];
#pragma unroll
        for (int j = 0; j < 4; j++) {
            int col = dj + tc * 4 + j;
            float c = acc[i][j];
            ev[j] = (row == col) ? (-0.5f * c) : (-c);
        }
        e.x = ev[0]; e.y = ev[1]; e.z = ev[2]; e.w = ev[3];
        *reinterpret_cast<float4*>(&g_E[(size_t)row * DIM + dj + tc * 4]) = e;
    }
}

// ---------------- K3: Gram tiles (bf16 mma) + fused trace epilogue -------
// 10 upper-triangular 128x128 tiles x 14 k-splits = 140 CTAs (one wave).
#define TKB 32
#define LDP 136           // bf16 pitch: 272B row stride -> conflict-free ldsm
#define NSPLIT 14
#define NCHUNK (BN / TKB) // 1024

__global__ __launch_bounds__(256) void k_gram() {
    __shared__ __nv_bfloat16 sA[2][TKB * LDP];
    __shared__ __nv_bfloat16 sB[2][TKB * LDP];
    __shared__ float red[256];

    const int tid  = threadIdx.x;
    const int bid  = blockIdx.x;
    const int tile = bid % 10;
    const int ks   = bid / 10;
    const int mt = c_mt[tile], nt = c_nt[tile];
    const bool diag = (mt == nt);
    const int m0 = mt * 128, n0 = nt * 128;
    const int ch0 = (ks * NCHUNK) / NSPLIT;
    const int ch1 = ((ks + 1) * NCHUNK) / NSPLIT;
    const int k0  = ch0 * TKB;
    const int nst = ch1 - ch0;            // 73 or 74 stages

    const int lane = tid & 31, warp = tid >> 5;
    const int wm0 = (warp >> 2) * 64;
    const int wn0 = (warp & 3) * 32;

    // ldmatrix lane mapping
    const int sub = lane >> 3, r8 = lane & 7;
    const int lmk = r8 + ((sub >> 1) << 3);
    const int lmc = (sub & 1) << 3;
    const unsigned lmoff = (unsigned)((lmk * LDP + lmc) * 2);

    float acc[4][4][4];
#pragma unroll
    for (int i = 0; i < 4; i++)
#pragma unroll
        for (int j = 0; j < 4; j++)
#pragma unroll
            for (int q = 0; q < 4; q++) acc[i][j][q] = 0.f;

    uint2 pa[4], pb[4];

    auto gload = [&](int s) {
#pragma unroll
        for (int i = 0; i < 4; i++) {
            int idx = tid + i * 256;              // 1024 uint2 per buffer
            int row = idx >> 5, c2 = idx & 31;    // 32 uint2 per 128-col row
            const __nv_bfloat16* base = g_xb + (size_t)(k0 + s * TKB + row) * DIM;
            pa[i] = reinterpret_cast<const uint2*>(base + m0)[c2];
            if (!diag) pb[i] = reinterpret_cast<const uint2*>(base + n0)[c2];
        }
    };
    auto sstore = [&](int buf) {
#pragma unroll
        for (int i = 0; i < 4; i++) {
            int idx = tid + i * 256;
            int row = idx >> 5, c2 = idx & 31;
            *reinterpret_cast<uint2*>(&sA[buf][row * LDP + c2 * 4]) = pa[i];
            if (!diag) *reinterpret_cast<uint2*>(&sB[buf][row * LDP + c2 * 4]) = pb[i];
        }
    };

    gload(0);
    sstore(0);
    __syncthreads();

    for (int s = 0; s < nst; s++) {
        const int buf = s & 1;
        if (s + 1 < nst) gload(s + 1);

        const unsigned baseA = smem_u32(&sA[buf][0]) + lmoff;
        const unsigned baseB = diag ? baseA : (smem_u32(&sB[buf][0]) + lmoff);
#pragma unroll
        for (int kk = 0; kk < TKB; kk += 16) {
            unsigned afr[4][4];
#pragma unroll
            for (int mi = 0; mi < 4; mi++)
                ldsm4t(afr[mi], baseA + (unsigned)((kk * LDP + wm0 + mi * 16) * 2));
            unsigned bq[2][4];
#pragma unroll
            for (int nb = 0; nb < 2; nb++)
                ldsm4t(bq[nb], baseB + (unsigned)((kk * LDP + wn0 + nb * 16) * 2));
#pragma unroll
            for (int mi = 0; mi < 4; mi++) {
                mma16816(acc[mi][0], afr[mi], bq[0][0], bq[0][2]);
                mma16816(acc[mi][1], afr[mi], bq[0][1], bq[0][3]);
                mma16816(acc[mi][2], afr[mi], bq[1][0], bq[1][2]);
                mma16816(acc[mi][3], afr[mi], bq[1][1], bq[1][3]);
            }
        }
        if (s + 1 < nst) sstore((s + 1) & 1);
        __syncthreads();
    }

    // ---- fused trace epilogue: partial = sum(acc .* E_tile) ----
    const int g = lane >> 2, t4 = lane & 3;
    float fsum = 0.f;
#pragma unroll
    for (int mi = 0; mi < 4; mi++) {
#pragma unroll
        for (int ni = 0; ni < 4; ni++) {
            int row0 = m0 + wm0 + mi * 16 + g;
            int col0 = n0 + wn0 + ni * 8 + 2 * t4;
            float2 e0 = *reinterpret_cast<const float2*>(&g_E[(size_t)row0 * DIM + col0]);
            float2 e1 = *reinterpret_cast<const float2*>(&g_E[(size_t)(row0 + 8) * DIM + col0]);
            fsum += acc[mi][ni][0] * e0.x + acc[mi][ni][1] * e0.y
                  + acc[mi][ni][2] * e1.x + acc[mi][ni][3] * e1.y;
        }
    }
    red[tid] = fsum;
    __syncthreads();
    for (int o = 128; o; o >>= 1) {
        if (tid < o) red[tid] += red[tid + o];
        __syncthreads();
    }
    if (tid == 0) {
        double w = diag ? 1.0 : 2.0;   // symmetry: off-diagonal tiles counted twice
        atomicAdd(&g_S, w * (double)red[0]);
    }
}

// ---------------- K4: broadcast-add the interaction scalar ----------------
__global__ void k_final(float* __restrict__ out) {
    int i = blockIdx.x * 256 + threadIdx.x;       // 128 blocks
    out[i] += (float)g_S;
}

// ---------------- launch ----------------
extern "C" void kernel_launch(void* const* d_in, const int* in_sizes, int n_in,
                              void* d_out, int out_size) {
    const float* x = (const float*)d_in[0];   // [256,128,512]
    const float* W = (const float*)d_in[1];   // [1,512]
    const float* b = (const float*)d_in[2];   // [1]
    const float* V = (const float*)d_in[3];   // [512,512]
    float* out = (float*)d_out;               // [32768,1]

    k_zero <<<1, 32>>>();
    k_E    <<<64, 256>>>(V);
    k_fuse <<<BN / 8, 256>>>(x, W, b, out);
    k_gram <<<10 * NSPLIT, 256>>>();
    k_final<<<BN / 256, 256>>>(out);
}

// round 4
// speedup vs baseline: 1.2295x; 1.1875x over previous
#include <cuda_runtime.h>
#include <cuda_bf16.h>
#include <cstdint>

// Problem constants (B=256, N=128, D=512)
#define BN    32768
#define DIM   512

// ---------------- device scratch (no allocations allowed) ----------------
__device__ __nv_bfloat16 g_xb[BN * DIM];   // bf16 copy of x (33.5 MB, fits L2)
__device__ float  g_E[DIM * DIM];          // E = 0.5*diag(r) - V V^T, fp32
__device__ double g_S;                     // sum G .* E  (the interaction scalar)

__device__ const int c_mt[10] = {0,0,0,0,1,1,1,2,2,3};
__device__ const int c_nt[10] = {0,1,2,3,1,2,3,2,3,3};

// ---------------- helpers ----------------
__device__ __forceinline__ unsigned smem_u32(const void* p) {
    return (unsigned)__cvta_generic_to_shared(p);
}
__device__ __forceinline__ unsigned pack_bf16x2(float a, float b) {
    __nv_bfloat162 h = __floats2bfloat162_rn(a, b);
    return *reinterpret_cast<unsigned*>(&h);
}
__device__ __forceinline__ void ldsm4t(unsigned* r, unsigned addr) {
    asm volatile("ldmatrix.sync.aligned.m8n8.x4.trans.shared.b16 {%0,%1,%2,%3}, [%4];"
                 : "=r"(r[0]), "=r"(r[1]), "=r"(r[2]), "=r"(r[3])
                 : "r"(addr));
}
__device__ __forceinline__ void mma16816(float* c, const unsigned* a, unsigned b0, unsigned b1) {
    asm volatile(
        "mma.sync.aligned.m16n8k16.row.col.f32.bf16.bf16.f32 "
        "{%0,%1,%2,%3}, {%4,%5,%6,%7}, {%8,%9}, {%0,%1,%2,%3};"
        : "+f"(c[0]), "+f"(c[1]), "+f"(c[2]), "+f"(c[3])
        : "r"(a[0]), "r"(a[1]), "r"(a[2]), "r"(a[3]), "r"(b0), "r"(b1));
}
__device__ __forceinline__ void cpasync16(unsigned saddr, const void* g) {
    asm volatile("cp.async.cg.shared.global [%0], [%1], 16;" :: "r"(saddr), "l"(g));
}
__device__ __forceinline__ void cp_commit() {
    asm volatile("cp.async.commit_group;");
}
template <int N>
__device__ __forceinline__ void cp_wait() {
    asm volatile("cp.async.wait_group %0;" :: "n"(N));
}

// ---------------- K1: merged prep ---------------------------------------
// blocks [0,64):   E = 0.5*diag(r) - V V^T  (64x64 tiles, fp32)
// blocks [64,4160): linear part + bf16 conversion (8 rows per block)
__global__ __launch_bounds__(256) void k_prep(const float* __restrict__ x,
                                              const float* __restrict__ W,
                                              const float* __restrict__ bias,
                                              const float* __restrict__ V,
                                              float* __restrict__ out) {
    __shared__ float sVa[32 * 68];
    __shared__ float sVb[32 * 68];
    const int tid = threadIdx.x;
    const int blk = blockIdx.x;

    if (blk < 64) {
        // ---------- E tile ----------
        if (blk == 0 && tid == 0) g_S = 0.0;
        const int di = (blk >> 3) * 64, dj = (blk & 7) * 64;
        const int tr = tid >> 4, tc = tid & 15;

        float acc[4][4];
#pragma unroll
        for (int i = 0; i < 4; i++)
#pragma unroll
            for (int j = 0; j < 4; j++) acc[i][j] = 0.f;

        for (int ch = 0; ch < 16; ch++) {
            __syncthreads();
#pragma unroll
            for (int i = 0; i < 8; i++) {
                int idx = tid + i * 256;
                int rr = idx >> 5, cc = idx & 31;
                sVa[cc * 68 + rr] = V[(size_t)(di + rr) * DIM + ch * 32 + cc];
                sVb[cc * 68 + rr] = V[(size_t)(dj + rr) * DIM + ch * 32 + cc];
            }
            __syncthreads();
#pragma unroll 4
            for (int ec = 0; ec < 32; ec++) {
                float4 av = reinterpret_cast<const float4*>(sVa)[ec * 17 + tr];
                float4 bv = reinterpret_cast<const float4*>(sVb)[ec * 17 + tc];
                float a4[4] = {av.x, av.y, av.z, av.w};
                float b4[4] = {bv.x, bv.y, bv.z, bv.w};
#pragma unroll
                for (int i = 0; i < 4; i++)
#pragma unroll
                    for (int j = 0; j < 4; j++) acc[i][j] += a4[i] * b4[j];
            }
        }
#pragma unroll
        for (int i = 0; i < 4; i++) {
            int row = di + tr * 4 + i;
            float ev[4];
#pragma unroll
            for (int j = 0; j < 4; j++) {
                int col = dj + tc * 4 + j;
                float c = acc[i][j];
                ev[j] = (row == col) ? (-0.5f * c) : (-c);
            }
            float4 e = {ev[0], ev[1], ev[2], ev[3]};
            *reinterpret_cast<float4*>(&g_E[(size_t)row * DIM + dj + tc * 4]) = e;
        }
    } else {
        // ---------- linear + bf16 convert ----------
        float* sW = sVa;   // reuse smem
        for (int i = tid; i < DIM; i += 256) sW[i] = W[i];
        __syncthreads();

        int warp = tid >> 5, lane = tid & 31;
        int row = (blk - 64) * 8 + warp;           // 4096 blocks * 8 rows
        const float4* xr = reinterpret_cast<const float4*>(x + (size_t)row * DIM);
        const float4* wr = reinterpret_cast<const float4*>(sW);
        uint2* xbr = reinterpret_cast<uint2*>(g_xb + (size_t)row * DIM);
        float s = 0.f;
#pragma unroll
        for (int j = 0; j < 4; j++) {
            float4 a = xr[lane + j * 32];
            float4 w = wr[lane + j * 32];
            s += a.x * w.x + a.y * w.y + a.z * w.z + a.w * w.w;
            uint2 p;
            p.x = pack_bf16x2(a.x, a.y);
            p.y = pack_bf16x2(a.z, a.w);
            xbr[lane + j * 32] = p;
        }
#pragma unroll
        for (int off = 16; off; off >>= 1) s += __shfl_xor_sync(0xffffffffu, s, off);
        if (lane == 0) out[row] = s + bias[0];
    }
}

// ---------------- K2: Gram tiles (bf16 mma, cp.async) + trace epilogue ---
// 10 upper-triangular 128x128 tiles x 28 k-splits = 280 CTAs (2 per SM).
#define TKB 32
#define LDP 136           // bf16 pitch: 272B row stride -> conflict-free ldsm
#define NSPLIT 28
#define NCHUNK (BN / TKB) // 1024

__global__ __launch_bounds__(256, 2) void k_gram() {
    __shared__ __align__(16) __nv_bfloat16 sA[2][TKB * LDP];
    __shared__ __align__(16) __nv_bfloat16 sB[2][TKB * LDP];
    __shared__ float red[256];

    const int tid  = threadIdx.x;
    const int bid  = blockIdx.x;
    const int tile = bid % 10;
    const int ks   = bid / 10;
    const int mt = c_mt[tile], nt = c_nt[tile];
    const bool diag = (mt == nt);
    const int m0 = mt * 128, n0 = nt * 128;
    const int ch0 = (ks * NCHUNK) / NSPLIT;
    const int ch1 = ((ks + 1) * NCHUNK) / NSPLIT;
    const int k0  = ch0 * TKB;
    const int nst = ch1 - ch0;            // 36 or 37 stages

    const int lane = tid & 31, warp = tid >> 5;
    const int wm0 = (warp >> 2) * 64;
    const int wn0 = (warp & 3) * 32;

    // ldmatrix lane mapping
    const int sub = lane >> 3, r8 = lane & 7;
    const int lmk = r8 + ((sub >> 1) << 3);
    const int lmc = (sub & 1) << 3;
    const unsigned lmoff = (unsigned)((lmk * LDP + lmc) * 2);

    // cp.async mapping: 512 16B-chunks per buffer; 2 per thread.
    // idx -> row = idx>>4 (0..31), c16 = idx&15 (16B chunk within 256B row)
    const int r0c = tid >> 4,         c0c = tid & 15;
    const int r1c = (tid + 256) >> 4, c1c = tid & 15;
    const unsigned soff0 = (unsigned)(r0c * (LDP * 2) + c0c * 16);
    const unsigned soff1 = (unsigned)(r1c * (LDP * 2) + c1c * 16);
    const char* gA0 = (const char*)(g_xb + (size_t)(k0 + r0c) * DIM + m0) + c0c * 16;
    const char* gA1 = (const char*)(g_xb + (size_t)(k0 + r1c) * DIM + m0) + c1c * 16;
    const char* gB0 = (const char*)(g_xb + (size_t)(k0 + r0c) * DIM + n0) + c0c * 16;
    const char* gB1 = (const char*)(g_xb + (size_t)(k0 + r1c) * DIM + n0) + c1c * 16;
    const unsigned sAb[2] = { smem_u32(&sA[0][0]), smem_u32(&sA[1][0]) };
    const unsigned sBb[2] = { smem_u32(&sB[0][0]), smem_u32(&sB[1][0]) };

    auto issue = [&](int s) {
        const int buf = s & 1;
        const size_t go = (size_t)s * (TKB * DIM * 2);   // bytes per stage
        cpasync16(sAb[buf] + soff0, gA0 + go);
        cpasync16(sAb[buf] + soff1, gA1 + go);
        if (!diag) {
            cpasync16(sBb[buf] + soff0, gB0 + go);
            cpasync16(sBb[buf] + soff1, gB1 + go);
        }
    };

    float acc[4][4][4];
#pragma unroll
    for (int i = 0; i < 4; i++)
#pragma unroll
        for (int j = 0; j < 4; j++)
#pragma unroll
            for (int q = 0; q < 4; q++) acc[i][j][q] = 0.f;

    issue(0);
    cp_commit();

    for (int s = 0; s < nst; s++) {
        const int buf = s & 1;
        if (s + 1 < nst) {
            issue(s + 1);
            cp_commit();
            cp_wait<1>();
        } else {
            cp_wait<0>();
        }
        __syncthreads();

        const unsigned baseA = sAb[buf] + lmoff;
        const unsigned baseB = (diag ? sAb[buf] : sBb[buf]) + lmoff;
#pragma unroll
        for (int kk = 0; kk < TKB; kk += 16) {
            unsigned afr[4][4];
#pragma unroll
            for (int mi = 0; mi < 4; mi++)
                ldsm4t(afr[mi], baseA + (unsigned)((kk * LDP + wm0 + mi * 16) * 2));
            unsigned bq[2][4];
#pragma unroll
            for (int nb = 0; nb < 2; nb++)
                ldsm4t(bq[nb], baseB + (unsigned)((kk * LDP + wn0 + nb * 16) * 2));
#pragma unroll
            for (int mi = 0; mi < 4; mi++) {
                mma16816(acc[mi][0], afr[mi], bq[0][0], bq[0][2]);
                mma16816(acc[mi][1], afr[mi], bq[0][1], bq[0][3]);
                mma16816(acc[mi][2], afr[mi], bq[1][0], bq[1][2]);
                mma16816(acc[mi][3], afr[mi], bq[1][1], bq[1][3]);
            }
        }
        __syncthreads();
    }

    // ---- fused trace epilogue: partial = sum(acc .* E_tile) ----
    const int g = lane >> 2, t4 = lane & 3;
    float fsum = 0.f;
#pragma unroll
    for (int mi = 0; mi < 4; mi++) {
#pragma unroll
        for (int ni = 0; ni < 4; ni++) {
            int row0 = m0 + wm0 + mi * 16 + g;
            int col0 = n0 + wn0 + ni * 8 + 2 * t4;
            float2 e0 = *reinterpret_cast<const float2*>(&g_E[(size_t)row0 * DIM + col0]);
            float2 e1 = *reinterpret_cast<const float2*>(&g_E[(size_t)(row0 + 8) * DIM + col0]);
            fsum += acc[mi][ni][0] * e0.x + acc[mi][ni][1] * e0.y
                  + acc[mi][ni][2] * e1.x + acc[mi][ni][3] * e1.y;
        }
    }
    red[tid] = fsum;
    __syncthreads();
    for (int o = 128; o; o >>= 1) {
        if (tid < o) red[tid] += red[tid + o];
        __syncthreads();
    }
    if (tid == 0) {
        double w = diag ? 1.0 : 2.0;   // symmetry: off-diagonal tiles counted twice
        atomicAdd(&g_S, w * (double)red[0]);
    }
}

// ---------------- K3: broadcast-add the interaction scalar ----------------
__global__ void k_final(float* __restrict__ out) {
    int i = blockIdx.x * 256 + threadIdx.x;       // 128 blocks
    out[i] += (float)g_S;
}

// ---------------- launch ----------------
extern "C" void kernel_launch(void* const* d_in, const int* in_sizes, int n_in,
                              void* d_out, int out_size) {
    const float* x = (const float*)d_in[0];   // [256,128,512]
    const float* W = (const float*)d_in[1];   // [1,512]
    const float* b = (const float*)d_in[2];   // [1]
    const float* V = (const float*)d_in[3];   // [512,512]
    float* out = (float*)d_out;               // [32768,1]

    k_prep <<<64 + BN / 8, 256>>>(x, W, b, V, out);
    k_gram <<<10 * NSPLIT, 256>>>();
    k_final<<<BN / 256, 256>>>(out);
}

// round 6
// speedup vs baseline: 1.6515x; 1.3432x over previous
#include <cuda_runtime.h>
#include <cuda_bf16.h>
#include <cstdint>

// Problem constants (B=256, N=128, D=512)
#define BN    32768
#define DIM   512

// ---------------- device scratch (no allocations allowed) ----------------
__device__ __nv_bfloat16 g_xb[BN * DIM];   // bf16 copy of x (33.5 MB, fits L2)
__device__ float  g_E[DIM * DIM];          // E = 0.5*diag(r) - V V^T, fp32
__device__ double g_S;                     // sum G .* E  (the interaction scalar)

__device__ const int c_mt[10] = {0,0,0,0,1,1,1,2,2,3};
__device__ const int c_nt[10] = {0,1,2,3,1,2,3,2,3,3};

// ---------------- helpers ----------------
__device__ __forceinline__ unsigned smem_u32(const void* p) {
    return (unsigned)__cvta_generic_to_shared(p);
}
__device__ __forceinline__ unsigned pack_bf16x2(float a, float b) {
    __nv_bfloat162 h = __floats2bfloat162_rn(a, b);
    return *reinterpret_cast<unsigned*>(&h);
}
__device__ __forceinline__ void ldsm4t(unsigned* r, unsigned addr) {
    asm volatile("ldmatrix.sync.aligned.m8n8.x4.trans.shared.b16 {%0,%1,%2,%3}, [%4];"
                 : "=r"(r[0]), "=r"(r[1]), "=r"(r[2]), "=r"(r[3])
                 : "r"(addr));
}
__device__ __forceinline__ void mma16816(float* c, const unsigned* a, unsigned b0, unsigned b1) {
    asm volatile(
        "mma.sync.aligned.m16n8k16.row.col.f32.bf16.bf16.f32 "
        "{%0,%1,%2,%3}, {%4,%5,%6,%7}, {%8,%9}, {%0,%1,%2,%3};"
        : "+f"(c[0]), "+f"(c[1]), "+f"(c[2]), "+f"(c[3])
        : "r"(a[0]), "r"(a[1]), "r"(a[2]), "r"(a[3]), "r"(b0), "r"(b1));
}
__device__ __forceinline__ void cpasync16(unsigned saddr, const void* g) {
    asm volatile("cp.async.cg.shared.global [%0], [%1], 16;" :: "r"(saddr), "l"(g));
}
__device__ __forceinline__ void cp_commit() {
    asm volatile("cp.async.commit_group;");
}
template <int N>
__device__ __forceinline__ void cp_wait() {
    asm volatile("cp.async.wait_group %0;" :: "n"(N));
}

// ---------------- K0: zero g_E + g_S ----------------
__global__ void k_zero() {
    int idx = blockIdx.x * 256 + threadIdx.x;      // 64 CTAs -> 16384 threads
    float4 z = {0.f, 0.f, 0.f, 0.f};
#pragma unroll
    for (int i = 0; i < 4; i++)
        reinterpret_cast<float4*>(g_E)[idx + i * 16384] = z;
    if (idx == 0) g_S = 0.0;
}

// ---------------- K1: merged prep ---------------------------------------
// blocks [0,256):   E partials (64 tiles x 4 e-splits) atomically into g_E
// blocks [256,2304): linear part + bf16 conversion (16 rows per block)
__global__ __launch_bounds__(256) void k_prep(const float* __restrict__ x,
                                              const float* __restrict__ W,
                                              const float* __restrict__ bias,
                                              const float* __restrict__ V,
                                              float* __restrict__ out) {
    __shared__ float sVa[32 * 68];
    __shared__ float sVb[32 * 68];
    const int tid = threadIdx.x;
    const int blk = blockIdx.x;

    if (blk < 256) {
        // ---------- E tile partial (e-range of 128) ----------
        const int tile = blk >> 2, es = blk & 3;
        const int di = (tile >> 3) * 64, dj = (tile & 7) * 64;
        const int e0 = es * 128;
        const int tr = tid >> 4, tc = tid & 15;

        float acc[4][4];
#pragma unroll
        for (int i = 0; i < 4; i++)
#pragma unroll
            for (int j = 0; j < 4; j++) acc[i][j] = 0.f;

        for (int ch = 0; ch < 4; ch++) {           // 4 chunks of 32 e-values
            __syncthreads();
#pragma unroll
            for (int i = 0; i < 8; i++) {
                int idx = tid + i * 256;
                int rr = idx >> 5, cc = idx & 31;
                sVa[cc * 68 + rr] = V[(size_t)(di + rr) * DIM + e0 + ch * 32 + cc];
                sVb[cc * 68 + rr] = V[(size_t)(dj + rr) * DIM + e0 + ch * 32 + cc];
            }
            __syncthreads();
#pragma unroll 4
            for (int ec = 0; ec < 32; ec++) {
                float4 av = reinterpret_cast<const float4*>(sVa)[ec * 17 + tr];
                float4 bv = reinterpret_cast<const float4*>(sVb)[ec * 17 + tc];
                float a4[4] = {av.x, av.y, av.z, av.w};
                float b4[4] = {bv.x, bv.y, bv.z, bv.w};
#pragma unroll
                for (int i = 0; i < 4; i++)
#pragma unroll
                    for (int j = 0; j < 4; j++) acc[i][j] += a4[i] * b4[j];
            }
        }
        // E = 0.5*diag(r) - C ; on diagonal the partial is -0.5*c
#pragma unroll
        for (int i = 0; i < 4; i++) {
            int row = di + tr * 4 + i;
#pragma unroll
            for (int j = 0; j < 4; j++) {
                int col = dj + tc * 4 + j;
                float c = acc[i][j];
                float e = (row == col) ? (-0.5f * c) : (-c);
                atomicAdd(&g_E[(size_t)row * DIM + col], e);
            }
        }
    } else {
        // ---------- linear + bf16 convert : 16 rows per CTA ----------
        float* sW = sVa;   // reuse smem
        for (int i = tid; i < DIM; i += 256) sW[i] = W[i];
        __syncthreads();

        const int warp = tid >> 5, lane = tid & 31;
        const int rbase = (blk - 256) * 16 + warp * 2;   // 2048 blocks * 16 rows
        const float4* wr = reinterpret_cast<const float4*>(sW);
        const float4 w0 = wr[2 * lane],      w1 = wr[2 * lane + 1];
        const float4 w2 = wr[64 + 2 * lane], w3 = wr[64 + 2 * lane + 1];

#pragma unroll
        for (int r = 0; r < 2; r++) {
            const int row = rbase + r;
            const float4* xr = reinterpret_cast<const float4*>(x + (size_t)row * DIM);
            uint4* xbr = reinterpret_cast<uint4*>(g_xb + (size_t)row * DIM);
            float4 a0 = xr[2 * lane], a1 = xr[2 * lane + 1];
            float4 a2 = xr[64 + 2 * lane], a3 = xr[64 + 2 * lane + 1];

            uint4 p0, p1;
            p0.x = pack_bf16x2(a0.x, a0.y); p0.y = pack_bf16x2(a0.z, a0.w);
            p0.z = pack_bf16x2(a1.x, a1.y); p0.w = pack_bf16x2(a1.z, a1.w);
            p1.x = pack_bf16x2(a2.x, a2.y); p1.y = pack_bf16x2(a2.z, a2.w);
            p1.z = pack_bf16x2(a3.x, a3.y); p1.w = pack_bf16x2(a3.z, a3.w);
            xbr[lane] = p0;
            xbr[32 + lane] = p1;

            float s0 = a0.x * w0.x + a0.y * w0.y + a0.z * w0.z + a0.w * w0.w;
            float s1 = a1.x * w1.x + a1.y * w1.y + a1.z * w1.z + a1.w * w1.w;
            float s2 = a2.x * w2.x + a2.y * w2.y + a2.z * w2.z + a2.w * w2.w;
            float s3 = a3.x * w3.x + a3.y * w3.y + a3.z * w3.z + a3.w * w3.w;
            float s = (s0 + s1) + (s2 + s3);
#pragma unroll
            for (int off = 16; off; off >>= 1) s += __shfl_xor_sync(0xffffffffu, s, off);
            if (lane == 0) out[row] = s + bias[0];
        }
    }
}

// ---------------- K2: Gram tiles (bf16 mma, cp.async) + trace epilogue ---
// 10 upper-triangular 128x128 tiles x 28 k-splits = 280 CTAs (2 per SM).
#define TKB 32
#define LDP 136           // bf16 pitch: 272B row stride -> conflict-free ldsm
#define NSPLIT 28
#define NCHUNK (BN / TKB) // 1024

__global__ __launch_bounds__(256, 2) void k_gram() {
    __shared__ __align__(16) __nv_bfloat16 sA[2][TKB * LDP];
    __shared__ __align__(16) __nv_bfloat16 sB[2][TKB * LDP];
    __shared__ float red[256];

    const int tid  = threadIdx.x;
    const int bid  = blockIdx.x;
    const int tile = bid % 10;
    const int ks   = bid / 10;
    const int mt = c_mt[tile], nt = c_nt[tile];
    const bool diag = (mt == nt);
    const int m0 = mt * 128, n0 = nt * 128;
    const int ch0 = (ks * NCHUNK) / NSPLIT;
    const int ch1 = ((ks + 1) * NCHUNK) / NSPLIT;
    const int k0  = ch0 * TKB;
    const int nst = ch1 - ch0;            // 36 or 37 stages

    const int lane = tid & 31, warp = tid >> 5;
    const int wm0 = (warp >> 2) * 64;
    const int wn0 = (warp & 3) * 32;

    // ldmatrix lane mapping
    const int sub = lane >> 3, r8 = lane & 7;
    const int lmk = r8 + ((sub >> 1) << 3);
    const int lmc = (sub & 1) << 3;
    const unsigned lmoff = (unsigned)((lmk * LDP + lmc) * 2);

    // cp.async mapping: 512 16B-chunks per buffer; 2 per thread.
    const int r0c = tid >> 4,         c0c = tid & 15;
    const int r1c = (tid + 256) >> 4, c1c = tid & 15;
    const unsigned soff0 = (unsigned)(r0c * (LDP * 2) + c0c * 16);
    const unsigned soff1 = (unsigned)(r1c * (LDP * 2) + c1c * 16);
    const char* gA0 = (const char*)(g_xb + (size_t)(k0 + r0c) * DIM + m0) + c0c * 16;
    const char* gA1 = (const char*)(g_xb + (size_t)(k0 + r1c) * DIM + m0) + c1c * 16;
    const char* gB0 = (const char*)(g_xb + (size_t)(k0 + r0c) * DIM + n0) + c0c * 16;
    const char* gB1 = (const char*)(g_xb + (size_t)(k0 + r1c) * DIM + n0) + c1c * 16;
    const unsigned sAb[2] = { smem_u32(&sA[0][0]), smem_u32(&sA[1][0]) };
    const unsigned sBb[2] = { smem_u32(&sB[0][0]), smem_u32(&sB[1][0]) };

    auto issue = [&](int s) {
        const int buf = s & 1;
        const size_t go = (size_t)s * (TKB * DIM * 2);   // bytes per stage
        cpasync16(sAb[buf] + soff0, gA0 + go);
        cpasync16(sAb[buf] + soff1, gA1 + go);
        if (!diag) {
            cpasync16(sBb[buf] + soff0, gB0 + go);
            cpasync16(sBb[buf] + soff1, gB1 + go);
        }
    };

    float acc[4][4][4];
#pragma unroll
    for (int i = 0; i < 4; i++)
#pragma unroll
        for (int j = 0; j < 4; j++)
#pragma unroll
            for (int q = 0; q < 4; q++) acc[i][j][q] = 0.f;

    issue(0);
    cp_commit();

    for (int s = 0; s < nst; s++) {
        const int buf = s & 1;
        if (s + 1 < nst) {
            issue(s + 1);
            cp_commit();
            cp_wait<1>();
        } else {
            cp_wait<0>();
        }
        __syncthreads();

        const unsigned baseA = sAb[buf] + lmoff;
        const unsigned baseB = (diag ? sAb[buf] : sBb[buf]) + lmoff;
#pragma unroll
        for (int kk = 0; kk < TKB; kk += 16) {
            unsigned afr[4][4];
#pragma unroll
            for (int mi = 0; mi < 4; mi++)
                ldsm4t(afr[mi], baseA + (unsigned)((kk * LDP + wm0 + mi * 16) * 2));
            unsigned bq[2][4];
#pragma unroll
            for (int nb = 0; nb < 2; nb++)
                ldsm4t(bq[nb], baseB + (unsigned)((kk * LDP + wn0 + nb * 16) * 2));
#pragma unroll
            for (int mi = 0; mi < 4; mi++) {
                mma16816(acc[mi][0], afr[mi], bq[0][0], bq[0][2]);
                mma16816(acc[mi][1], afr[mi], bq[0][1], bq[0][3]);
                mma16816(acc[mi][2], afr[mi], bq[1][0], bq[1][2]);
                mma16816(acc[mi][3], afr[mi], bq[1][1], bq[1][3]);
            }
        }
        __syncthreads();
    }

    // ---- fused trace epilogue: partial = sum(acc .* E_tile) ----
    const int g = lane >> 2, t4 = lane & 3;
    float fsum = 0.f;
#pragma unroll
    for (int mi = 0; mi < 4; mi++) {
#pragma unroll
        for (int ni = 0; ni < 4; ni++) {
            int row0 = m0 + wm0 + mi * 16 + g;
            int col0 = n0 + wn0 + ni * 8 + 2 * t4;
            float2 e0 = *reinterpret_cast<const float2*>(&g_E[(size_t)row0 * DIM + col0]);
            float2 e1 = *reinterpret_cast<const float2*>(&g_E[(size_t)(row0 + 8) * DIM + col0]);
            fsum += acc[mi][ni][0] * e0.x + acc[mi][ni][1] * e0.y
                  + acc[mi][ni][2] * e1.x + acc[mi][ni][3] * e1.y;
        }
    }
    red[tid] = fsum;
    __syncthreads();
    for (int o = 128; o; o >>= 1) {
        if (tid < o) red[tid] += red[tid + o];
        __syncthreads();
    }
    if (tid == 0) {
        double w = diag ? 1.0 : 2.0;   // symmetry: off-diagonal tiles counted twice
        atomicAdd(&g_S, w * (double)red[0]);
    }
}

// ---------------- K3: broadcast-add the interaction scalar ----------------
__global__ void k_final(float* __restrict__ out) {
    int i = blockIdx.x * 256 + threadIdx.x;       // 128 blocks
    out[i] += (float)g_S;
}

// ---------------- launch ----------------
extern "C" void kernel_launch(void* const* d_in, const int* in_sizes, int n_in,
                              void* d_out, int out_size) {
    const float* x = (const float*)d_in[0];   // [256,128,512]
    const float* W = (const float*)d_in[1];   // [1,512]
    const float* b = (const float*)d_in[2];   // [1]
    const float* V = (const float*)d_in[3];   // [512,512]
    float* out = (float*)d_out;               // [32768,1]

    k_zero <<<64, 256>>>();
    k_prep <<<256 + BN / 16, 256>>>(x, W, b, V, out);
    k_gram <<<10 * NSPLIT, 256>>>();
    k_final<<<BN / 256, 256>>>(out);
}